// round 2
// baseline (speedup 1.0000x reference)
#include <cuda_runtime.h>

#define NL 3
#define NB 64
#define NS 512
#define ND 1024
#define NH 512
#define G3 1536
#define MR (NB*NS)   // 32768 rows

// ---------------- device scratch (no allocation allowed) ----------------
__device__ __align__(128) float g_Gxf[(size_t)MR * G3];
__device__ __align__(128) float g_Gxb[(size_t)MR * G3];
__device__ __align__(128) float g_O  [(size_t)MR * 1024];
__device__ __align__(128) float g_HW [(size_t)MR * 1024];
__device__ __align__(128) float g_h[2][2][NH * NB];   // [dir][pingpong][k*64+b]
__device__ unsigned g_cnt[2];
__device__ unsigned g_phs[2];

__device__ __forceinline__ float sigf(float x)  { return 1.f / (1.f + __expf(-x)); }
__device__ __forceinline__ float tanh_(float x) { return 2.f / (1.f + __expf(-2.f * x)) - 1.f; }

// ================= SGEMM: C = A[M,K] @ B[K,N] + bias ====================
// HIGHWAY epilogue (needs K==N): g = sigmoid(C); dest = g*A + (1-g)*prev
template<bool HIGHWAY>
__global__ void __launch_bounds__(256, 2)
sgemm(const float* __restrict__ A, const float* __restrict__ Bw,
      const float* __restrict__ bias, float* __restrict__ Cd,
      const float* __restrict__ prev, int M, int N, int K)
{
    __shared__ float As[8][128];
    __shared__ float Bs[8][128];
    const int t = threadIdx.x;
    const int row0 = blockIdx.y * 128, col0 = blockIdx.x * 128;
    const int arow = t >> 1, acol = (t & 1) * 4;
    const int brow = t >> 5, bcol = (t & 31) * 4;
    const int tx = t & 15,  ty = t >> 4;

    const float* Ap = A + (size_t)(row0 + arow) * K + acol;
    const float* Bp = Bw + (size_t)brow * N + col0 + bcol;

    float acc[8][8];
#pragma unroll
    for (int i = 0; i < 8; i++)
#pragma unroll
        for (int j = 0; j < 8; j++) acc[i][j] = 0.f;

    float4 av = *(const float4*)Ap;
    float4 bv = *(const float4*)Bp;

    for (int kt = 0; kt < K; kt += 8) {
        __syncthreads();
        As[acol + 0][arow] = av.x;
        As[acol + 1][arow] = av.y;
        As[acol + 2][arow] = av.z;
        As[acol + 3][arow] = av.w;
        *(float4*)&Bs[brow][bcol] = bv;
        __syncthreads();
        if (kt + 8 < K) {
            av = *(const float4*)(Ap + kt + 8);
            bv = *(const float4*)(Bp + (size_t)(kt + 8) * N);
        }
#pragma unroll
        for (int kk = 0; kk < 8; kk++) {
            float a[8], b[8];
            *(float4*)&a[0] = *(const float4*)&As[kk][ty * 4];
            *(float4*)&a[4] = *(const float4*)&As[kk][64 + ty * 4];
            *(float4*)&b[0] = *(const float4*)&Bs[kk][tx * 4];
            *(float4*)&b[4] = *(const float4*)&Bs[kk][64 + tx * 4];
#pragma unroll
            for (int i = 0; i < 8; i++)
#pragma unroll
                for (int j = 0; j < 8; j++)
                    acc[i][j] += a[i] * b[j];
        }
    }

#pragma unroll
    for (int i = 0; i < 8; i++) {
        size_t r = (size_t)row0 + (i >> 2) * 64 + ty * 4 + (i & 3);
#pragma unroll
        for (int jh = 0; jh < 2; jh++) {
            int c = col0 + jh * 64 + tx * 4;
            float4 bb = *(const float4*)&bias[c];
            float4 v;
            v.x = acc[i][jh * 4 + 0] + bb.x;
            v.y = acc[i][jh * 4 + 1] + bb.y;
            v.z = acc[i][jh * 4 + 2] + bb.z;
            v.w = acc[i][jh * 4 + 3] + bb.w;
            if (HIGHWAY) {
                float4 o4 = *(const float4*)&A[r * N + c];     // K==N: A row == O row
                float4 p4 = *(const float4*)&prev[r * N + c];
                float gx = sigf(v.x), gy = sigf(v.y), gz = sigf(v.z), gw = sigf(v.w);
                v.x = gx * o4.x + (1.f - gx) * p4.x;
                v.y = gy * o4.y + (1.f - gy) * p4.y;
                v.z = gz * o4.z + (1.f - gz) * p4.z;
                v.w = gw * o4.w + (1.f - gw) * p4.w;
            }
            *(float4*)&Cd[r * N + c] = v;
        }
    }
}

// ================= persistent recurrent kernel ===========================
// grid = 128 blocks: blocks [0,64) = forward dir, [64,128) = backward dir.
// Block owns 8 hidden units (24 gate columns), all 64 batches.
__device__ __forceinline__ void gridbar(int d, unsigned target)
{
    __syncthreads();
    if (threadIdx.x == 0) {
        __threadfence();
        unsigned a = atomicAdd(&g_cnt[d], 1);
        if (a == 63) {
            atomicExch(&g_cnt[d], 0);
            __threadfence();
            atomicAdd(&g_phs[d], 1);
        } else {
            while ((int)(*(volatile unsigned*)&g_phs[d] - target) < 0) { }
            __threadfence();
        }
    }
    __syncthreads();
}

__global__ void lstm_rec(const float* __restrict__ Wf, const float* __restrict__ Wb,
                         const float* __restrict__ h0f, const float* __restrict__ c0f,
                         const float* __restrict__ h0b, const float* __restrict__ c0b)
{
    extern __shared__ float sm[];
    float* Whs = sm;              // [24][512]   48 KB
    float* hs  = sm + 24 * 512;   // [2][64][64] 32 KB

    const int t = threadIdx.x;
    const int w = t >> 5;         // warp 0..7 -> local unit
    const int lane = t & 31;      // batches lane, lane+32
    const int bx = blockIdx.x;
    const int d  = bx >> 6;
    const int u0 = (bx & 63) * 8;

    const float* W  = d ? Wb : Wf;
    const float* Gx = d ? g_Gxb : g_Gxf;
    const float* h0 = d ? h0b : h0f;
    const float* c0 = d ? c0b : c0f;

    // load this block's Wh slice (rows 1024.. of W) into SMEM, [col][k]
    for (int lc = 0; lc < 24; lc++) {
        int gcol = (lc % 3) * 512 + u0 + lc / 3;
        for (int k = t; k < 512; k += 256)
            Whs[lc * 512 + k] = W[(size_t)(1024 + k) * 1536 + gcol];
    }

    // init cell state (broadcast over batch) and publish h0
    float cc0 = c0[u0 + w], cc1 = cc0;
    float h0v = h0[u0 + w];
    g_h[d][0][(u0 + w) * 64 + lane]      = h0v;
    g_h[d][0][(u0 + w) * 64 + lane + 32] = h0v;

    unsigned ep = *(volatile unsigned*)&g_phs[d];   // stable at launch
    unsigned nb = 1;
    gridbar(d, ep + nb);   // all h0 published

    int pp = 0;
    for (int step = 0; step < 512; step++) {
        const int s = d ? (511 - step) : step;

        // x-part gates (latency hidden behind the FMA mainloop)
        size_t base0 = ((size_t)lane * 512 + s) * 1536 + u0 + w;
        size_t base1 = base0 + (size_t)32 * 512 * 1536;
        float gi0 = __ldg(&Gx[base0]);
        float gj0 = __ldg(&Gx[base0 + 512]);
        float go0 = __ldg(&Gx[base0 + 1024]);
        float gi1 = __ldg(&Gx[base1]);
        float gj1 = __ldg(&Gx[base1 + 512]);
        float go1 = __ldg(&Gx[base1 + 1024]);

        float ai0 = 0, aj0 = 0, ao0 = 0, ai1 = 0, aj1 = 0, ao1 = 0;
        const float4* hsrc = (const float4*)g_h[d][pp];   // 8192 float4

        // stage chunk 0
        float4 pre[4];
#pragma unroll
        for (int i = 0; i < 4; i++) pre[i] = __ldcg(hsrc + t + i * 256);
#pragma unroll
        for (int i = 0; i < 4; i++) ((float4*)hs)[t + i * 256] = pre[i];
        __syncthreads();

        for (int ch = 0; ch < 8; ch++) {
            const int cur = ch & 1;
            if (ch < 7) {
#pragma unroll
                for (int i = 0; i < 4; i++)
                    pre[i] = __ldcg(hsrc + (ch + 1) * 1024 + t + i * 256);
            }
            const float* hbuf = hs + cur * 4096;
            const float* w0p = Whs + (w * 3 + 0) * 512 + ch * 64;
            const float* w1p = Whs + (w * 3 + 1) * 512 + ch * 64;
            const float* w2p = Whs + (w * 3 + 2) * 512 + ch * 64;
#pragma unroll
            for (int kk = 0; kk < 64; kk++) {
                float w0 = w0p[kk], w1 = w1p[kk], w2 = w2p[kk];
                float hv0 = hbuf[kk * 64 + lane];
                float hv1 = hbuf[kk * 64 + lane + 32];
                ai0 += hv0 * w0; aj0 += hv0 * w1; ao0 += hv0 * w2;
                ai1 += hv1 * w0; aj1 += hv1 * w1; ao1 += hv1 * w2;
            }
            if (ch < 7) {
                __syncthreads();
#pragma unroll
                for (int i = 0; i < 4; i++)
                    ((float4*)(hs + (cur ^ 1) * 4096))[t + i * 256] = pre[i];
                __syncthreads();
            }
        }

        // coupled-gate cell update
        float i0 = sigf(ai0 + gi0), j0 = tanh_(aj0 + gj0), o0 = sigf(ao0 + go0);
        cc0 = (1.f - i0) * cc0 + i0 * j0;
        float hn0 = tanh_(cc0) * o0;
        float i1 = sigf(ai1 + gi1), j1 = tanh_(aj1 + gj1), o1 = sigf(ao1 + go1);
        cc1 = (1.f - i1) * cc1 + i1 * j1;
        float hn1 = tanh_(cc1) * o1;

        g_h[d][pp ^ 1][(u0 + w) * 64 + lane]      = hn0;
        g_h[d][pp ^ 1][(u0 + w) * 64 + lane + 32] = hn1;

        size_t o0i = ((size_t)lane * 512 + s) * 1024 + d * 512 + u0 + w;
        size_t o1i = ((size_t)(lane + 32) * 512 + s) * 1024 + d * 512 + u0 + w;
        g_O[o0i] = hn0;
        g_O[o1i] = hn1;

        pp ^= 1;
        nb++;
        gridbar(d, ep + nb);
    }
}

// ================= launcher =============================================
extern "C" void kernel_launch(void* const* d_in, const int* in_sizes, int n_in,
                              void* d_out, int out_size)
{
    const float* x      = (const float*)d_in[0];
    const float* fw_W   = (const float*)d_in[1];
    const float* fw_b   = (const float*)d_in[2];
    const float* bw_W   = (const float*)d_in[3];
    const float* bw_b   = (const float*)d_in[4];
    const float* h0f    = (const float*)d_in[5];
    const float* c0f    = (const float*)d_in[6];
    const float* h0b    = (const float*)d_in[7];
    const float* c0b    = (const float*)d_in[8];
    const float* proj_W = (const float*)d_in[9];
    const float* proj_b = (const float*)d_in[10];
    const float* in_pW  = (const float*)d_in[11];
    const float* in_pb  = (const float*)d_in[12];
    float* out = (float*)d_out;

    float *Gxf, *Gxb, *O, *HW;
    cudaGetSymbolAddress((void**)&Gxf, g_Gxf);
    cudaGetSymbolAddress((void**)&Gxb, g_Gxb);
    cudaGetSymbolAddress((void**)&O,   g_O);
    cudaGetSymbolAddress((void**)&HW,  g_HW);

    const int REC_SMEM = (24 * 512 + 2 * 64 * 64) * 4;   // 81920 B
    cudaFuncSetAttribute(lstm_rec, cudaFuncAttributeMaxDynamicSharedMemorySize, REC_SMEM);

    // highway residual seed: HW = x @ in_proj_W + in_proj_b
    sgemm<false><<<dim3(1024 / 128, MR / 128), 256>>>(x, in_pW, in_pb, HW, nullptr, MR, 1024, 1024);

    for (int l = 0; l < NL; l++) {
        const float* IN = (l == 0) ? x : HW;
        const float* Wfl = fw_W + (size_t)l * G3 * G3;
        const float* Wbl = bw_W + (size_t)l * G3 * G3;

        sgemm<false><<<dim3(G3 / 128, MR / 128), 256>>>(IN, Wfl, fw_b + l * G3, Gxf, nullptr, MR, G3, 1024);
        sgemm<false><<<dim3(G3 / 128, MR / 128), 256>>>(IN, Wbl, bw_b + l * G3, Gxb, nullptr, MR, G3, 1024);

        lstm_rec<<<128, 256, REC_SMEM>>>(Wfl, Wbl,
                                         h0f + l * NH, c0f + l * NH,
                                         h0b + l * NH, c0b + l * NH);

        float* dest = (l == NL - 1) ? out : HW;
        sgemm<true><<<dim3(1024 / 128, MR / 128), 256>>>(O, proj_W + (size_t)l * 1024 * 1024,
                                                         proj_b + l * 1024, dest, HW, MR, 1024, 1024);
    }
}

// round 3
// speedup vs baseline: 1.2069x; 1.2069x over previous
#include <cuda_runtime.h>
#include <cstdint>

#define NL 3
#define NB 64
#define NS 512
#define ND 1024
#define NH 512
#define G3 1536
#define MR (NB*NS)   // 32768 rows

// ---------------- device scratch (no allocation allowed) ----------------
__device__ __align__(128) float g_Gxf[(size_t)MR * G3];
__device__ __align__(128) float g_Gxb[(size_t)MR * G3];
__device__ __align__(128) float g_O  [(size_t)MR * 1024];
__device__ __align__(128) float g_HW [(size_t)MR * 1024];
__device__ __align__(128) float g_h[2][2][NH * NB];   // [dir][pingpong][k*64+b]
__device__ unsigned g_cnt[2];
__device__ unsigned g_phs[2];

__device__ __forceinline__ float sigf(float x)  { return 1.f / (1.f + __expf(-x)); }
__device__ __forceinline__ float tanh_(float x) { return 2.f / (1.f + __expf(-2.f * x)) - 1.f; }

__device__ __forceinline__ uint32_t f2tf(float f) {
    uint32_t u;
    asm("cvt.rna.tf32.f32 %0, %1;" : "=r"(u) : "f"(f));
    return u;
}

__device__ __forceinline__ void mma_tf32(float* c, const uint32_t* a, const uint32_t* b) {
    asm volatile(
        "mma.sync.aligned.m16n8k8.row.col.f32.tf32.tf32.f32 "
        "{%0,%1,%2,%3}, {%4,%5,%6,%7}, {%8,%9}, {%0,%1,%2,%3};\n"
        : "+f"(c[0]), "+f"(c[1]), "+f"(c[2]), "+f"(c[3])
        : "r"(a[0]), "r"(a[1]), "r"(a[2]), "r"(a[3]), "r"(b[0]), "r"(b[1]));
}

// ============ tf32 tensor-core GEMM: C = A[M,K] @ B[K,N] + bias ==========
// HIGHWAY epilogue (needs K==N): g = sigmoid(C); dest = g*A + (1-g)*prev
#define APAD 20
#define BPAD 136
template<bool HIGHWAY>
__global__ void __launch_bounds__(256)
tgemm(const float* __restrict__ A, const float* __restrict__ Bw,
      const float* __restrict__ bias, float* __restrict__ Cd,
      const float* __restrict__ prev, int M, int N, int K)
{
    __shared__ uint32_t As[128][APAD];   // [m][k], padded, conflict-free frags
    __shared__ uint32_t Bs[16][BPAD];    // [k][n], padded

    const int t = threadIdx.x;
    const int w = t >> 5, lane = t & 31;
    const int row0 = blockIdx.y * 128, col0 = blockIdx.x * 128;
    const int warm = (w >> 2) * 64;   // warp m offset in tile
    const int warn = (w & 3) * 32;    // warp n offset in tile
    const int lr = lane >> 2;         // 0..7
    const int lc = lane & 3;          // 0..3

    // global load addressing: A 2 rows/thread-pair, B 16 rows
    const int ar = t >> 1, ac = (t & 1) * 8;
    const int br = t >> 4, bc = (t & 15) * 8;
    const float* Ap = A + (size_t)(row0 + ar) * K + ac;
    const float* Bp = Bw + (size_t)br * N + col0 + bc;

    float4 av0 = *(const float4*)Ap;
    float4 av1 = *(const float4*)(Ap + 4);
    float4 bv0 = *(const float4*)Bp;
    float4 bv1 = *(const float4*)(Bp + 4);

    float acc[4][4][4];
#pragma unroll
    for (int i = 0; i < 4; i++)
#pragma unroll
        for (int j = 0; j < 4; j++)
#pragma unroll
            for (int r = 0; r < 4; r++) acc[i][j][r] = 0.f;

    for (int kt = 0; kt < K; kt += 16) {
        __syncthreads();
        {   // store tiles converted to tf32; A as 8B-aligned uint2 pairs
            uint2 u;
            u.x = f2tf(av0.x); u.y = f2tf(av0.y); *(uint2*)&As[ar][ac]     = u;
            u.x = f2tf(av0.z); u.y = f2tf(av0.w); *(uint2*)&As[ar][ac + 2] = u;
            u.x = f2tf(av1.x); u.y = f2tf(av1.y); *(uint2*)&As[ar][ac + 4] = u;
            u.x = f2tf(av1.z); u.y = f2tf(av1.w); *(uint2*)&As[ar][ac + 6] = u;
            uint4 v;
            v.x = f2tf(bv0.x); v.y = f2tf(bv0.y); v.z = f2tf(bv0.z); v.w = f2tf(bv0.w);
            *(uint4*)&Bs[br][bc] = v;
            v.x = f2tf(bv1.x); v.y = f2tf(bv1.y); v.z = f2tf(bv1.z); v.w = f2tf(bv1.w);
            *(uint4*)&Bs[br][bc + 4] = v;
        }
        __syncthreads();
        if (kt + 16 < K) {
            av0 = *(const float4*)(Ap + kt + 16);
            av1 = *(const float4*)(Ap + kt + 20);
            bv0 = *(const float4*)(Bp + (size_t)(kt + 16) * N);
            bv1 = *(const float4*)(Bp + (size_t)(kt + 16) * N + 4);
        }
#pragma unroll
        for (int ks = 0; ks < 16; ks += 8) {
            uint32_t af[4][4], bf[4][2];
#pragma unroll
            for (int mt = 0; mt < 4; mt++) {
                int r = warm + mt * 16 + lr;
                af[mt][0] = As[r][ks + lc];
                af[mt][1] = As[r + 8][ks + lc];
                af[mt][2] = As[r][ks + lc + 4];
                af[mt][3] = As[r + 8][ks + lc + 4];
            }
#pragma unroll
            for (int nt = 0; nt < 4; nt++) {
                int cB = warn + nt * 8 + lr;
                bf[nt][0] = Bs[ks + lc][cB];
                bf[nt][1] = Bs[ks + lc + 4][cB];
            }
#pragma unroll
            for (int mt = 0; mt < 4; mt++)
#pragma unroll
                for (int nt = 0; nt < 4; nt++)
                    mma_tf32(acc[mt][nt], af[mt], bf[nt]);
        }
    }

    // ---------------- epilogue ----------------
#pragma unroll
    for (int mt = 0; mt < 4; mt++) {
#pragma unroll
        for (int half = 0; half < 2; half++) {
            size_t r = (size_t)row0 + warm + mt * 16 + lr + half * 8;
#pragma unroll
            for (int nt = 0; nt < 4; nt++) {
                int c = col0 + warn + nt * 8 + 2 * lc;
                float vx = acc[mt][nt][half * 2 + 0] + __ldg(&bias[c]);
                float vy = acc[mt][nt][half * 2 + 1] + __ldg(&bias[c + 1]);
                if (HIGHWAY) {
                    float2 o2 = *(const float2*)&A[r * N + c];
                    float2 p2 = *(const float2*)&prev[r * N + c];
                    float gx = sigf(vx), gy = sigf(vy);
                    vx = gx * o2.x + (1.f - gx) * p2.x;
                    vy = gy * o2.y + (1.f - gy) * p2.y;
                }
                float2 out2; out2.x = vx; out2.y = vy;
                *(float2*)&Cd[r * N + c] = out2;
            }
        }
    }
}

// ================= persistent recurrent kernel ===========================
// grid = 128 blocks: blocks [0,64) = forward dir, [64,128) = backward dir.
__device__ __forceinline__ void gridbar(int d, unsigned target)
{
    __syncthreads();
    if (threadIdx.x == 0) {
        __threadfence();
        unsigned a = atomicAdd(&g_cnt[d], 1);
        if (a == 63) {
            atomicExch(&g_cnt[d], 0);
            __threadfence();
            atomicAdd(&g_phs[d], 1);
        } else {
            while ((int)(*(volatile unsigned*)&g_phs[d] - target) < 0) { }
            __threadfence();
        }
    }
    __syncthreads();
}

__global__ void lstm_rec(const float* __restrict__ Wf, const float* __restrict__ Wb,
                         const float* __restrict__ h0f, const float* __restrict__ c0f,
                         const float* __restrict__ h0b, const float* __restrict__ c0b)
{
    extern __shared__ float sm[];
    float* Whs = sm;              // [24][512]   48 KB
    float* hs  = sm + 24 * 512;   // [2][64][64] 32 KB

    const int t = threadIdx.x;
    const int w = t >> 5;
    const int lane = t & 31;
    const int bx = blockIdx.x;
    const int d  = bx >> 6;
    const int u0 = (bx & 63) * 8;

    const float* W  = d ? Wb : Wf;
    const float* Gx = d ? g_Gxb : g_Gxf;
    const float* h0 = d ? h0b : h0f;
    const float* c0 = d ? c0b : c0f;

    for (int lc = 0; lc < 24; lc++) {
        int gcol = (lc % 3) * 512 + u0 + lc / 3;
        for (int k = t; k < 512; k += 256)
            Whs[lc * 512 + k] = W[(size_t)(1024 + k) * 1536 + gcol];
    }

    float cc0 = c0[u0 + w], cc1 = cc0;
    float h0v = h0[u0 + w];
    g_h[d][0][(u0 + w) * 64 + lane]      = h0v;
    g_h[d][0][(u0 + w) * 64 + lane + 32] = h0v;

    unsigned ep = *(volatile unsigned*)&g_phs[d];
    unsigned nb = 1;
    gridbar(d, ep + nb);

    int pp = 0;
    for (int step = 0; step < 512; step++) {
        const int s = d ? (511 - step) : step;

        size_t base0 = ((size_t)lane * 512 + s) * 1536 + u0 + w;
        size_t base1 = base0 + (size_t)32 * 512 * 1536;
        float gi0 = __ldg(&Gx[base0]);
        float gj0 = __ldg(&Gx[base0 + 512]);
        float go0 = __ldg(&Gx[base0 + 1024]);
        float gi1 = __ldg(&Gx[base1]);
        float gj1 = __ldg(&Gx[base1 + 512]);
        float go1 = __ldg(&Gx[base1 + 1024]);

        float ai0 = 0, aj0 = 0, ao0 = 0, ai1 = 0, aj1 = 0, ao1 = 0;
        const float4* hsrc = (const float4*)g_h[d][pp];

        float4 pre[4];
#pragma unroll
        for (int i = 0; i < 4; i++) pre[i] = __ldcg(hsrc + t + i * 256);
#pragma unroll
        for (int i = 0; i < 4; i++) ((float4*)hs)[t + i * 256] = pre[i];
        __syncthreads();

        for (int ch = 0; ch < 8; ch++) {
            const int cur = ch & 1;
            if (ch < 7) {
#pragma unroll
                for (int i = 0; i < 4; i++)
                    pre[i] = __ldcg(hsrc + (ch + 1) * 1024 + t + i * 256);
            }
            const float* hbuf = hs + cur * 4096;
            const float* w0p = Whs + (w * 3 + 0) * 512 + ch * 64;
            const float* w1p = Whs + (w * 3 + 1) * 512 + ch * 64;
            const float* w2p = Whs + (w * 3 + 2) * 512 + ch * 64;
#pragma unroll
            for (int kk = 0; kk < 64; kk++) {
                float w0 = w0p[kk], w1 = w1p[kk], w2 = w2p[kk];
                float hv0 = hbuf[kk * 64 + lane];
                float hv1 = hbuf[kk * 64 + lane + 32];
                ai0 += hv0 * w0; aj0 += hv0 * w1; ao0 += hv0 * w2;
                ai1 += hv1 * w0; aj1 += hv1 * w1; ao1 += hv1 * w2;
            }
            if (ch < 7) {
                __syncthreads();
#pragma unroll
                for (int i = 0; i < 4; i++)
                    ((float4*)(hs + (cur ^ 1) * 4096))[t + i * 256] = pre[i];
                __syncthreads();
            }
        }

        float i0 = sigf(ai0 + gi0), j0 = tanh_(aj0 + gj0), o0 = sigf(ao0 + go0);
        cc0 = (1.f - i0) * cc0 + i0 * j0;
        float hn0 = tanh_(cc0) * o0;
        float i1 = sigf(ai1 + gi1), j1 = tanh_(aj1 + gj1), o1 = sigf(ao1 + go1);
        cc1 = (1.f - i1) * cc1 + i1 * j1;
        float hn1 = tanh_(cc1) * o1;

        g_h[d][pp ^ 1][(u0 + w) * 64 + lane]      = hn0;
        g_h[d][pp ^ 1][(u0 + w) * 64 + lane + 32] = hn1;

        size_t o0i = ((size_t)lane * 512 + s) * 1024 + d * 512 + u0 + w;
        size_t o1i = ((size_t)(lane + 32) * 512 + s) * 1024 + d * 512 + u0 + w;
        g_O[o0i] = hn0;
        g_O[o1i] = hn1;

        pp ^= 1;
        nb++;
        gridbar(d, ep + nb);
    }
}

// ================= launcher =============================================
extern "C" void kernel_launch(void* const* d_in, const int* in_sizes, int n_in,
                              void* d_out, int out_size)
{
    const float* x      = (const float*)d_in[0];
    const float* fw_W   = (const float*)d_in[1];
    const float* fw_b   = (const float*)d_in[2];
    const float* bw_W   = (const float*)d_in[3];
    const float* bw_b   = (const float*)d_in[4];
    const float* h0f    = (const float*)d_in[5];
    const float* c0f    = (const float*)d_in[6];
    const float* h0b    = (const float*)d_in[7];
    const float* c0b    = (const float*)d_in[8];
    const float* proj_W = (const float*)d_in[9];
    const float* proj_b = (const float*)d_in[10];
    const float* in_pW  = (const float*)d_in[11];
    const float* in_pb  = (const float*)d_in[12];
    float* out = (float*)d_out;

    float *Gxf, *Gxb, *O, *HW;
    cudaGetSymbolAddress((void**)&Gxf, g_Gxf);
    cudaGetSymbolAddress((void**)&Gxb, g_Gxb);
    cudaGetSymbolAddress((void**)&O,   g_O);
    cudaGetSymbolAddress((void**)&HW,  g_HW);

    const int REC_SMEM = (24 * 512 + 2 * 64 * 64) * 4;   // 81920 B
    cudaFuncSetAttribute(lstm_rec, cudaFuncAttributeMaxDynamicSharedMemorySize, REC_SMEM);

    // highway residual seed: HW = x @ in_proj_W + in_proj_b
    tgemm<false><<<dim3(1024 / 128, MR / 128), 256>>>(x, in_pW, in_pb, HW, nullptr, MR, 1024, 1024);

    for (int l = 0; l < NL; l++) {
        const float* IN = (l == 0) ? x : HW;
        const float* Wfl = fw_W + (size_t)l * G3 * G3;
        const float* Wbl = bw_W + (size_t)l * G3 * G3;

        tgemm<false><<<dim3(G3 / 128, MR / 128), 256>>>(IN, Wfl, fw_b + l * G3, Gxf, nullptr, MR, G3, 1024);
        tgemm<false><<<dim3(G3 / 128, MR / 128), 256>>>(IN, Wbl, bw_b + l * G3, Gxb, nullptr, MR, G3, 1024);

        lstm_rec<<<128, 256, REC_SMEM>>>(Wfl, Wbl,
                                         h0f + l * NH, c0f + l * NH,
                                         h0b + l * NH, c0b + l * NH);

        float* dest = (l == NL - 1) ? out : HW;
        tgemm<true><<<dim3(1024 / 128, MR / 128), 256>>>(O, proj_W + (size_t)l * 1024 * 1024,
                                                         proj_b + l * 1024, dest, HW, MR, 1024, 1024);
    }
}

// round 5
// speedup vs baseline: 1.2975x; 1.0751x over previous
#include <cuda_runtime.h>
#include <cstdint>

#define NL 3
#define NB 64
#define NS 512
#define ND 1024
#define NH 512
#define G3 1536
#define MR (NB*NS)   // 32768 rows
#define KK 1024      // K of every parallel GEMM

// ---------------- device scratch (no allocation allowed) ----------------
__device__ __align__(128) float g_Gxf[(size_t)MR * G3];
__device__ __align__(128) float g_Gxb[(size_t)MR * G3];
__device__ __align__(128) float g_O  [(size_t)MR * 1024];
__device__ __align__(128) float g_HW [(size_t)MR * 1024];
__device__ __align__(128) float g_WTf[(size_t)G3 * KK];     // transposed x-part weights
__device__ __align__(128) float g_WTb[(size_t)G3 * KK];
__device__ __align__(128) float g_WTp[(size_t)1024 * KK];   // transposed proj / in_proj
__device__ __align__(128) float g_h[2][2][NH * NB];
__device__ unsigned g_cnt[2];
__device__ unsigned g_phs[2];

__device__ __forceinline__ float sigf(float x)  { return 1.f / (1.f + __expf(-x)); }
__device__ __forceinline__ float tanh_(float x) { return 2.f / (1.f + __expf(-2.f * x)) - 1.f; }

__device__ __forceinline__ uint32_t smem_u32(const void* p) {
    uint32_t a;
    asm("{ .reg .u64 t; cvta.to.shared.u64 t, %1; cvt.u32.u64 %0, t; }" : "=r"(a) : "l"(p));
    return a;
}

__device__ __forceinline__ void mma_tf32(float* c, const uint32_t* a, const uint32_t* b) {
    asm volatile(
        "mma.sync.aligned.m16n8k8.row.col.f32.tf32.tf32.f32 "
        "{%0,%1,%2,%3}, {%4,%5,%6,%7}, {%8,%9}, {%0,%1,%2,%3};\n"
        : "+f"(c[0]), "+f"(c[1]), "+f"(c[2]), "+f"(c[3])
        : "r"(a[0]), "r"(a[1]), "r"(a[2]), "r"(a[3]), "r"(b[0]), "r"(b[1]));
}

__device__ __forceinline__ void cp16(uint32_t dst, const void* src) {
    asm volatile("cp.async.cg.shared.global [%0], [%1], 16;" :: "r"(dst), "l"(src));
}
#define CP_COMMIT() asm volatile("cp.async.commit_group;" ::: "memory")
#define CP_WAIT2()  asm volatile("cp.async.wait_group 2;" ::: "memory")

// ============== weight transpose: D[c][r] = S[r][c] =====================
__global__ void transp(const float* __restrict__ S, float* __restrict__ D,
                       int spitch, int rows, int cols)
{
    __shared__ float tl[32][33];
    const int c0 = blockIdx.x * 32, r0 = blockIdx.y * 32;
    const int tx = threadIdx.x, ty = threadIdx.y;
#pragma unroll
    for (int i = ty; i < 32; i += 8)
        tl[i][tx] = S[(size_t)(r0 + i) * spitch + c0 + tx];
    __syncthreads();
#pragma unroll
    for (int i = ty; i < 32; i += 8)
        D[(size_t)(c0 + i) * rows + r0 + tx] = tl[tx][i];
}

// ====== tf32 mma.sync GEMM, cp.async 4-stage: Cd = A[M,K]@BT[N,K]^T + b ==
// HIGHWAY (K==N): g = sigmoid(.); Cd = g*A + (1-g)*prev
// smem: 4 stages x (A 16KB + B 16KB) = 128KB. CTA 128x128, kstage 32.
#define SMB (4 * 32768)
template<bool HIGHWAY>
__global__ void __launch_bounds__(256)
tgemm(const float* __restrict__ A, const float* __restrict__ BT,
      const float* __restrict__ bias, float* __restrict__ Cd,
      const float* __restrict__ prev, int N)
{
    extern __shared__ char sm_[];
    const uint32_t sbase = smem_u32(sm_);

    const int t = threadIdx.x;
    const int w = t >> 5, lane = t & 31;
    const int lr = lane >> 2, lc = lane & 3;
    const int row0 = blockIdx.y * 128, col0 = blockIdx.x * 128;
    const int wm = (w & 1) * 64, wn = (w >> 1) * 32;

    // ---- cp.async per-thread granule mapping (1024 granules per operand) --
    size_t  srcOff[4];
    uint32_t dstOff[4];
#pragma unroll
    for (int j = 0; j < 4; j++) {
        int G = t + j * 256;
        int row = G >> 3, g = G & 7;
        srcOff[j] = (size_t)row * KK + g * 4;
        dstOff[j] = row * 128 + ((g ^ (row & 7)) << 4);
    }
    const float* Ag = A + (size_t)row0 * KK;
    const float* Bg = BT + (size_t)col0 * KK;

    // ---- fragment base addresses (swizzle folded to one XOR per load) ----
    // element (r,k): off = r*128 + lc*4 + ((r&7)<<4)  ^  (k8*32)  [^16 for k+4]
    uint32_t abase[4][2], bbase[4];
#pragma unroll
    for (int mt = 0; mt < 4; mt++) {
        int r1 = wm + mt * 16 + lr;
        abase[mt][0] = r1 * 128 + lc * 4 + ((r1 & 7) << 4);
        int r2 = r1 + 8;
        abase[mt][1] = r2 * 128 + lc * 4 + ((r2 & 7) << 4);
    }
#pragma unroll
    for (int nt = 0; nt < 4; nt++) {
        int n = wn + nt * 8 + lr;
        bbase[nt] = n * 128 + lc * 4 + ((n & 7) << 4);
    }

    float acc[4][4][4];
#pragma unroll
    for (int i = 0; i < 4; i++)
#pragma unroll
        for (int j = 0; j < 4; j++)
#pragma unroll
            for (int r = 0; r < 4; r++) acc[i][j][r] = 0.f;

    // ---- prologue: stages 0,1,2 in flight ----
#pragma unroll
    for (int s = 0; s < 3; s++) {
        uint32_t aB = sbase + s * 32768, bB = aB + 16384;
        int kt = s * 32;
#pragma unroll
        for (int j = 0; j < 4; j++) {
            cp16(aB + dstOff[j], Ag + srcOff[j] + kt);
            cp16(bB + dstOff[j], Bg + srcOff[j] + kt);
        }
        CP_COMMIT();
    }

    const int NKI = KK / 32;   // 32
    for (int i = 0; i < NKI; i++) {
        CP_WAIT2();
        __syncthreads();

        if (i + 3 < NKI) {
            int s = (i + 3) & 3, kt = (i + 3) * 32;
            uint32_t aB = sbase + s * 32768, bB = aB + 16384;
#pragma unroll
            for (int j = 0; j < 4; j++) {
                cp16(aB + dstOff[j], Ag + srcOff[j] + kt);
                cp16(bB + dstOff[j], Bg + srcOff[j] + kt);
            }
        }
        CP_COMMIT();

        const char* aS = sm_ + (i & 3) * 32768;
        const char* bS = aS + 16384;
#pragma unroll
        for (int k8 = 0; k8 < 4; k8++) {
            const uint32_t kx = k8 * 32;
            uint32_t af[4][4], bf[4][2];
#pragma unroll
            for (int mt = 0; mt < 4; mt++) {
                af[mt][0] = *(const uint32_t*)(aS + (abase[mt][0] ^ kx));
                af[mt][1] = *(const uint32_t*)(aS + (abase[mt][1] ^ kx));
                af[mt][2] = *(const uint32_t*)(aS + (abase[mt][0] ^ kx ^ 16));
                af[mt][3] = *(const uint32_t*)(aS + (abase[mt][1] ^ kx ^ 16));
            }
#pragma unroll
            for (int nt = 0; nt < 4; nt++) {
                bf[nt][0] = *(const uint32_t*)(bS + (bbase[nt] ^ kx));
                bf[nt][1] = *(const uint32_t*)(bS + (bbase[nt] ^ kx ^ 16));
            }
#pragma unroll
            for (int mt = 0; mt < 4; mt++)
#pragma unroll
                for (int nt = 0; nt < 4; nt++)
                    mma_tf32(acc[mt][nt], af[mt], bf[nt]);
        }
    }

    // ---------------- epilogue ----------------
#pragma unroll
    for (int mt = 0; mt < 4; mt++) {
#pragma unroll
        for (int half = 0; half < 2; half++) {
            size_t r = (size_t)row0 + wm + mt * 16 + lr + half * 8;
#pragma unroll
            for (int nt = 0; nt < 4; nt++) {
                int c = col0 + wn + nt * 8 + 2 * lc;
                float vx = acc[mt][nt][half * 2 + 0] + __ldg(&bias[c]);
                float vy = acc[mt][nt][half * 2 + 1] + __ldg(&bias[c + 1]);
                if (HIGHWAY) {
                    float2 o2 = *(const float2*)&A[r * N + c];
                    float2 p2 = *(const float2*)&prev[r * N + c];
                    float gx = sigf(vx), gy = sigf(vy);
                    vx = gx * o2.x + (1.f - gx) * p2.x;
                    vy = gy * o2.y + (1.f - gy) * p2.y;
                }
                float2 out2; out2.x = vx; out2.y = vy;
                *(float2*)&Cd[r * N + c] = out2;
            }
        }
    }
}

// ================= persistent recurrent kernel (unchanged) ==============
__device__ __forceinline__ void gridbar(int d, unsigned target)
{
    __syncthreads();
    if (threadIdx.x == 0) {
        __threadfence();
        unsigned a = atomicAdd(&g_cnt[d], 1);
        if (a == 63) {
            atomicExch(&g_cnt[d], 0);
            __threadfence();
            atomicAdd(&g_phs[d], 1);
        } else {
            while ((int)(*(volatile unsigned*)&g_phs[d] - target) < 0) { }
            __threadfence();
        }
    }
    __syncthreads();
}

__global__ void lstm_rec(const float* __restrict__ Wf, const float* __restrict__ Wb,
                         const float* __restrict__ h0f, const float* __restrict__ c0f,
                         const float* __restrict__ h0b, const float* __restrict__ c0b)
{
    extern __shared__ float sm[];
    float* Whs = sm;              // [24][512]
    float* hs  = sm + 24 * 512;   // [2][64][64]

    const int t = threadIdx.x;
    const int w = t >> 5;
    const int lane = t & 31;
    const int bx = blockIdx.x;
    const int d  = bx >> 6;
    const int u0 = (bx & 63) * 8;

    const float* W  = d ? Wb : Wf;
    const float* Gx = d ? g_Gxb : g_Gxf;
    const float* h0 = d ? h0b : h0f;
    const float* c0 = d ? c0b : c0f;

    for (int lc = 0; lc < 24; lc++) {
        int gcol = (lc % 3) * 512 + u0 + lc / 3;
        for (int k = t; k < 512; k += 256)
            Whs[lc * 512 + k] = W[(size_t)(1024 + k) * 1536 + gcol];
    }

    float cc0 = c0[u0 + w], cc1 = cc0;
    float h0v = h0[u0 + w];
    g_h[d][0][(u0 + w) * 64 + lane]      = h0v;
    g_h[d][0][(u0 + w) * 64 + lane + 32] = h0v;

    unsigned ep = *(volatile unsigned*)&g_phs[d];
    unsigned nb = 1;
    gridbar(d, ep + nb);

    int pp = 0;
    for (int step = 0; step < 512; step++) {
        const int s = d ? (511 - step) : step;

        size_t base0 = ((size_t)lane * 512 + s) * 1536 + u0 + w;
        size_t base1 = base0 + (size_t)32 * 512 * 1536;
        float gi0 = __ldg(&Gx[base0]);
        float gj0 = __ldg(&Gx[base0 + 512]);
        float go0 = __ldg(&Gx[base0 + 1024]);
        float gi1 = __ldg(&Gx[base1]);
        float gj1 = __ldg(&Gx[base1 + 512]);
        float go1 = __ldg(&Gx[base1 + 1024]);

        float ai0 = 0, aj0 = 0, ao0 = 0, ai1 = 0, aj1 = 0, ao1 = 0;
        const float4* hsrc = (const float4*)g_h[d][pp];

        float4 pre[4];
#pragma unroll
        for (int i = 0; i < 4; i++) pre[i] = __ldcg(hsrc + t + i * 256);
#pragma unroll
        for (int i = 0; i < 4; i++) ((float4*)hs)[t + i * 256] = pre[i];
        __syncthreads();

        for (int ch = 0; ch < 8; ch++) {
            const int cur = ch & 1;
            if (ch < 7) {
#pragma unroll
                for (int i = 0; i < 4; i++)
                    pre[i] = __ldcg(hsrc + (ch + 1) * 1024 + t + i * 256);
            }
            const float* hbuf = hs + cur * 4096;
            const float* w0p = Whs + (w * 3 + 0) * 512 + ch * 64;
            const float* w1p = Whs + (w * 3 + 1) * 512 + ch * 64;
            const float* w2p = Whs + (w * 3 + 2) * 512 + ch * 64;
#pragma unroll
            for (int kk = 0; kk < 64; kk++) {
                float w0 = w0p[kk], w1 = w1p[kk], w2 = w2p[kk];
                float hv0 = hbuf[kk * 64 + lane];
                float hv1 = hbuf[kk * 64 + lane + 32];
                ai0 += hv0 * w0; aj0 += hv0 * w1; ao0 += hv0 * w2;
                ai1 += hv1 * w0; aj1 += hv1 * w1; ao1 += hv1 * w2;
            }
            if (ch < 7) {
                __syncthreads();
#pragma unroll
                for (int i = 0; i < 4; i++)
                    ((float4*)(hs + (cur ^ 1) * 4096))[t + i * 256] = pre[i];
                __syncthreads();
            }
        }

        float i0 = sigf(ai0 + gi0), j0 = tanh_(aj0 + gj0), o0 = sigf(ao0 + go0);
        cc0 = (1.f - i0) * cc0 + i0 * j0;
        float hn0 = tanh_(cc0) * o0;
        float i1 = sigf(ai1 + gi1), j1 = tanh_(aj1 + gj1), o1 = sigf(ao1 + go1);
        cc1 = (1.f - i1) * cc1 + i1 * j1;
        float hn1 = tanh_(cc1) * o1;

        g_h[d][pp ^ 1][(u0 + w) * 64 + lane]      = hn0;
        g_h[d][pp ^ 1][(u0 + w) * 64 + lane + 32] = hn1;

        size_t o0i = ((size_t)lane * 512 + s) * 1024 + d * 512 + u0 + w;
        size_t o1i = ((size_t)(lane + 32) * 512 + s) * 1024 + d * 512 + u0 + w;
        g_O[o0i] = hn0;
        g_O[o1i] = hn1;

        pp ^= 1;
        nb++;
        gridbar(d, ep + nb);
    }
}

// ================= launcher =============================================
extern "C" void kernel_launch(void* const* d_in, const int* in_sizes, int n_in,
                              void* d_out, int out_size)
{
    const float* x      = (const float*)d_in[0];
    const float* fw_W   = (const float*)d_in[1];
    const float* fw_b   = (const float*)d_in[2];
    const float* bw_W   = (const float*)d_in[3];
    const float* bw_b   = (const float*)d_in[4];
    const float* h0f    = (const float*)d_in[5];
    const float* c0f    = (const float*)d_in[6];
    const float* h0b    = (const float*)d_in[7];
    const float* c0b    = (const float*)d_in[8];
    const float* proj_W = (const float*)d_in[9];
    const float* proj_b = (const float*)d_in[10];
    const float* in_pW  = (const float*)d_in[11];
    const float* in_pb  = (const float*)d_in[12];
    float* out = (float*)d_out;

    float *Gxf, *Gxb, *O, *HW, *WTf, *WTb, *WTp;
    cudaGetSymbolAddress((void**)&Gxf, g_Gxf);
    cudaGetSymbolAddress((void**)&Gxb, g_Gxb);
    cudaGetSymbolAddress((void**)&O,   g_O);
    cudaGetSymbolAddress((void**)&HW,  g_HW);
    cudaGetSymbolAddress((void**)&WTf, g_WTf);
    cudaGetSymbolAddress((void**)&WTb, g_WTb);
    cudaGetSymbolAddress((void**)&WTp, g_WTp);

    const int REC_SMEM = (24 * 512 + 2 * 64 * 64) * 4;
    cudaFuncSetAttribute(lstm_rec, cudaFuncAttributeMaxDynamicSharedMemorySize, REC_SMEM);
    cudaFuncSetAttribute(tgemm<false>, cudaFuncAttributeMaxDynamicSharedMemorySize, SMB);
    cudaFuncSetAttribute(tgemm<true>,  cudaFuncAttributeMaxDynamicSharedMemorySize, SMB);

    const dim3 TB(32, 8);

    // in_proj seed: HW = x @ in_proj_W + b
    transp<<<dim3(1024 / 32, 1024 / 32), TB>>>(in_pW, WTp, 1024, 1024, 1024);
    tgemm<false><<<dim3(8, MR / 128), 256, SMB>>>(x, WTp, in_pb, HW, nullptr, 1024);

    for (int l = 0; l < NL; l++) {
        const float* IN = (l == 0) ? x : HW;
        const float* Wfl = fw_W + (size_t)l * G3 * G3;
        const float* Wbl = bw_W + (size_t)l * G3 * G3;

        transp<<<dim3(G3 / 32, KK / 32), TB>>>(Wfl, WTf, G3, KK, G3);
        transp<<<dim3(G3 / 32, KK / 32), TB>>>(Wbl, WTb, G3, KK, G3);
        transp<<<dim3(1024 / 32, 1024 / 32), TB>>>(proj_W + (size_t)l * 1024 * 1024, WTp, 1024, 1024, 1024);

        tgemm<false><<<dim3(G3 / 128, MR / 128), 256, SMB>>>(IN, WTf, fw_b + l * G3, Gxf, nullptr, G3);
        tgemm<false><<<dim3(G3 / 128, MR / 128), 256, SMB>>>(IN, WTb, bw_b + l * G3, Gxb, nullptr, G3);

        lstm_rec<<<128, 256, REC_SMEM>>>(Wfl, Wbl,
                                         h0f + l * NH, c0f + l * NH,
                                         h0b + l * NH, c0b + l * NH);

        float* dest = (l == NL - 1) ? out : HW;
        tgemm<true><<<dim3(8, MR / 128), 256, SMB>>>(O, WTp, proj_b + l * 1024, dest, HW, 1024);
    }
}